// round 9
// baseline (speedup 1.0000x reference)
#include <cuda_runtime.h>
#include <cuda_fp16.h>
#include <cstdint>

#define Nn    512
#define NN    (Nn * Nn)
#define BATCH 64
#define KCH   64
#define NCHUNK (Nn / KCH)        // 8
#define BM 128
#define BN 64
#define MAT_A 16384              // 128 rows x 128B [ArH k32 | AiH k32]
#define MAT_X 8192               // 64 rows x 128B [XrH k32 | XiH k32]
#define SUB_B (MAT_A + MAT_X)    // 24576 per k32 sub-chunk
#define STG_B (2 * SUB_B)        // 49152 per k64 chunk
#define NSTG 2
#define SMEM_BYTES (NSTG * STG_B + 1024)

// ---------------- global scratch ----------------
__device__ __half g_xt_h[(size_t)BATCH * 2 * NN];   // X^T single fp16
__device__ __half g_s0_h[(size_t)BATCH * 2 * NN];   // S ping-pong, single fp16
__device__ __half g_s1_h[(size_t)BATCH * 2 * NN];
__device__ __half g_c7_h[(size_t)2 * NN];

// ---------------- helpers ----------------
__device__ __forceinline__ uint32_t smem_u32(const void* p) {
    uint32_t a;
    asm("{ .reg .u64 t; cvta.to.shared.u64 t, %1; cvt.u32.u64 %0, t; }" : "=r"(a) : "l"(p));
    return a;
}
#define CP_ASYNC16(dst, src) \
    asm volatile("cp.async.cg.shared.global [%0], [%1], 16;" :: "r"(dst), "l"(src))
#define CP_COMMIT()  asm volatile("cp.async.commit_group;" ::: "memory")
#define CP_WAIT0()   asm volatile("cp.async.wait_group 0;" ::: "memory")

__device__ __forceinline__ void ldsm4(uint32_t* r, uint32_t addr) {
    asm volatile("ldmatrix.sync.aligned.m8n8.x4.shared.b16 {%0,%1,%2,%3}, [%4];"
                 : "=r"(r[0]), "=r"(r[1]), "=r"(r[2]), "=r"(r[3]) : "r"(addr));
}
__device__ __forceinline__ void mma16816(float* d, const uint32_t* a, const uint32_t* b) {
    asm volatile(
        "mma.sync.aligned.m16n8k16.row.col.f32.f16.f16.f32 "
        "{%0,%1,%2,%3}, {%4,%5,%6,%7}, {%8,%9}, {%0,%1,%2,%3};"
        : "+f"(d[0]), "+f"(d[1]), "+f"(d[2]), "+f"(d[3])
        : "r"(a[0]), "r"(a[1]), "r"(a[2]), "r"(a[3]), "r"(b[0]), "r"(b[1]));
}

// ---------------------------------------------------------------------------
// Precompute: transpose X, single fp16
// ---------------------------------------------------------------------------
__global__ void x_transpose_h(const float* __restrict__ x,
                              __half* __restrict__ xh)
{
    __shared__ float t[32][33];
    const int z  = blockIdx.z;
    const int k0 = blockIdx.y * 32;
    const int n0 = blockIdx.x * 32;
    const int tx = threadIdx.x & 31, ty = threadIdx.x >> 5;
    const long zb = (long)z * NN;
    #pragma unroll
    for (int i = 0; i < 4; ++i)
        t[ty + 8 * i][tx] = x[zb + (long)(k0 + ty + 8 * i) * Nn + n0 + tx];
    __syncthreads();
    #pragma unroll
    for (int i = 0; i < 4; ++i) {
        const int n = n0 + ty + 8 * i, k = k0 + tx;
        xh[zb + (long)n * Nn + k] = __float2half_rn(t[tx][ty + 8 * i]);
    }
}

__global__ void conv_c7(const float* __restrict__ c7, __half* __restrict__ h)
{
    const int i = blockIdx.x * 256 + threadIdx.x;
    if (i < 2 * NN) h[i] = __float2half_rn(c7[i]);
}

// ---------------------------------------------------------------------------
// Fused complex GEMM, single-fp16 operands (4 passes):
//   accD = Ar.Xr + (-Ai).Xi ; accM = Ai.Xr + Ar.Xi
// CTA 128x64, 8 warps (4m x 2n), warp tile 32x32, 2 CTAs/SM,
// k64 chunks (two k32 sub-chunks per barrier), 2-stage cp.async pipeline:
//   loop: WAIT0 -> sync -> issue(c+1) -> compute(c)
// Target stage of issue(c+1) was freed by the sync (chunk c-1 readers done);
// chunk c+1 latency is hidden by chunk c's compute (~4000 cyc).
// ---------------------------------------------------------------------------
__global__ void __launch_bounds__(256, 2) cgemm_mma(
    const __half* __restrict__ aH, long aStride,
    const __half* __restrict__ xH,
    const float* __restrict__ C,
    float* __restrict__ outF,
    __half* __restrict__ outH,
    int isFinal)
{
    extern __shared__ char smraw[];
    const uint32_t sbase = (smem_u32(smraw) + 1023) & ~1023u;

    const int tid  = threadIdx.x;
    const int lane = tid & 31, wid = tid >> 5;
    const int warp_m = wid & 3;          // 4 m-tiles of 32 rows
    const int warp_n = wid >> 2;         // 2 n-tiles of 32 cols
    const int b  = blockIdx.z;
    const int bn = blockIdx.x * BN;
    const int bm = blockIdx.y * BM;

    // Per-CTA k-phase: decorrelate barrier timing of co-resident CTAs.
    const int phase =
        (int)(((blockIdx.x + blockIdx.y * 8u + blockIdx.z * 32u) * 5u) & 7u);

    // ---- cp.async per-thread constants: 6 x 16B per sub-chunk ----
    const int q = tid & 7, rowt = tid >> 3;   // q: 16B chunk in 128B row, rowt: 0..31
    const int comp = (q >= 4);
    const __half* srcs[6];
    uint32_t dsts[6];
    #pragma unroll
    for (int it = 0; it < 6; ++it) {
        if (it < 4) {                          // A: rows rowt + it*32 (0..127)
            const int row = rowt + it * 32;
            srcs[it] = aH + (long)b * aStride + (long)comp * NN
                     + (long)(bm + row) * Nn + (q & 3) * 8;
            dsts[it] = ((uint32_t)(row * 128 + q * 16)) ^ (uint32_t)((row & 7) << 4);
        } else {                               // X: rows rowt + (it-4)*32 (0..63)
            const int row = rowt + (it - 4) * 32;
            srcs[it] = xH + ((long)(2 * b) + comp) * NN
                     + (long)(bn + row) * Nn + (q & 3) * 8;
            dsts[it] = (uint32_t)MAT_A +
                       (((uint32_t)(row * 128 + q * 16)) ^ (uint32_t)((row & 7) << 4));
        }
    }

    auto issue = [&](int c) {
        const uint32_t sd = sbase + (uint32_t)(c & 1) * STG_B;
        const long kadd = (long)(((c + phase) & (NCHUNK - 1)) * KCH);
        #pragma unroll
        for (int sub = 0; sub < 2; ++sub) {
            const uint32_t so = sd + (uint32_t)sub * SUB_B;
            const long ko = kadd + sub * 32;
            #pragma unroll
            for (int it = 0; it < 6; ++it)
                CP_ASYNC16(so + dsts[it], srcs[it] + ko);
        }
        CP_COMMIT();
    };

    // ---- ldmatrix per-lane constants ----
    const uint32_t amask = (uint32_t)((lane & 7) << 4);
    const uint32_t abase = (uint32_t)((warp_m * 32 + (lane & 15)) * 128 + (lane >> 4) * 16);
    const uint32_t brow  = (uint32_t)((lane & 7) | ((lane >> 1) & 8));
    const uint32_t bcol  = (uint32_t)(((lane >> 3) & 1) * 16);

    float accD[2][4][4], accM[2][4][4];
    #pragma unroll
    for (int i = 0; i < 2; ++i)
        #pragma unroll
        for (int j = 0; j < 4; ++j)
            #pragma unroll
            for (int k = 0; k < 4; ++k) { accD[i][j][k] = 0.f; accM[i][j][k] = 0.f; }

    issue(0);

    for (int c = 0; c < NCHUNK; ++c) {
        CP_WAIT0();                 // chunk c landed (only group outstanding)
        __syncthreads();            // all warps done reading stage (c+1)&1 (chunk c-1)
        if (c + 1 < NCHUNK) issue(c + 1);

        const uint32_t st = sbase + (uint32_t)(c & 1) * STG_B;
        #pragma unroll
        for (int sub = 0; sub < 2; ++sub) {
            const uint32_t ss = st + (uint32_t)sub * SUB_B;
            #pragma unroll
            for (int sl = 0; sl < 2; ++sl) {
                uint32_t ar[2][4], ai[2][4], an[2][4];
                #pragma unroll
                for (int mt = 0; mt < 2; ++mt) {
                    const uint32_t rh =
                        (abase + (uint32_t)mt * 2048u + (uint32_t)sl * 32u) ^ amask;
                    ldsm4(ar[mt], ss + rh);             // Ar half
                    ldsm4(ai[mt], ss + (rh ^ 64u));     // Ai half
                    #pragma unroll
                    for (int j = 0; j < 4; ++j) an[mt][j] = ai[mt][j] ^ 0x80008000u;
                }

                #pragma unroll
                for (int ng = 0; ng < 2; ++ng) {
                    const uint32_t bb =
                        ((uint32_t)((warp_n * 32 + ng * 16 + brow) * 128) + bcol
                         + (uint32_t)sl * 32u) ^ amask;
                    uint32_t br[4], bi[4];
                    ldsm4(br, ss + (uint32_t)MAT_A + bb);            // Xr half
                    ldsm4(bi, ss + (uint32_t)MAT_A + (bb ^ 64u));    // Xi half
                    #pragma unroll
                    for (int mt = 0; mt < 2; ++mt)
                        #pragma unroll
                        for (int nt = 0; nt < 2; ++nt) {
                            float* dd = accD[mt][ng * 2 + nt];
                            float* mm = accM[mt][ng * 2 + nt];
                            mma16816(dd, ar[mt], br + nt * 2);
                            mma16816(dd, an[mt], bi + nt * 2);
                            mma16816(mm, ai[mt], br + nt * 2);
                            mma16816(mm, ar[mt], bi + nt * 2);
                        }
                }
            }
        }
    }

    // ---- epilogue: Dr = accD + Cr ; Di = accM + Ci ----
    const int tq = lane >> 2, tr = (lane & 3) * 2;
    #pragma unroll
    for (int mt = 0; mt < 2; ++mt)
        #pragma unroll
        for (int j = 0; j < 4; ++j)
            #pragma unroll
            for (int h = 0; h < 2; ++h) {
                const int r  = bm + warp_m * 32 + mt * 16 + h * 8 + tq;
                const int c0 = bn + warp_n * 32 + j * 8 + tr;
                const long co = (long)r * Nn + c0;
                const float2 cr = *(const float2*)(C + co);
                const float2 ci = *(const float2*)(C + NN + co);
                const float vr0 = accD[mt][j][2*h]   + cr.x;
                const float vr1 = accD[mt][j][2*h+1] + cr.y;
                const float vi0 = accM[mt][j][2*h]   + ci.x;
                const float vi1 = accM[mt][j][2*h+1] + ci.y;
                const long or_ = ((long)b * 2 + 0) * NN + co;
                const long oi_ = ((long)b * 2 + 1) * NN + co;
                if (isFinal) {
                    *(float2*)(outF + or_) = make_float2(vr0, vr1);
                    *(float2*)(outF + oi_) = make_float2(vi0, vi1);
                } else {
                    __half2 hv;
                    hv.x = __float2half_rn(vr0); hv.y = __float2half_rn(vr1);
                    *(__half2*)(outH + or_) = hv;
                    hv.x = __float2half_rn(vi0); hv.y = __float2half_rn(vi1);
                    *(__half2*)(outH + oi_) = hv;
                }
            }
}

// ---------------------------------------------------------------------------
extern "C" void kernel_launch(void* const* d_in, const int* in_sizes, int n_in,
                              void* d_out, int out_size)
{
    const float* x      = (const float*)d_in[0];
    const float* coeffs = (const float*)d_in[1];
    if (n_in >= 2 && in_sizes[0] == 8 * 2 * NN) {
        const float* t = x; x = coeffs; coeffs = t;
    }

    __half *xtH, *s0H, *s1H, *c7H;
    cudaGetSymbolAddress((void**)&xtH, g_xt_h);
    cudaGetSymbolAddress((void**)&s0H, g_s0_h);
    cudaGetSymbolAddress((void**)&s1H, g_s1_h);
    cudaGetSymbolAddress((void**)&c7H, g_c7_h);

    cudaFuncSetAttribute(cgemm_mma, cudaFuncAttributeMaxDynamicSharedMemorySize, SMEM_BYTES);

    x_transpose_h<<<dim3(16, 16, 128), 256>>>(x, xtH);
    conv_c7<<<(2 * NN + 255) / 256, 256>>>(coeffs + (long)7 * 2 * NN, c7H);

    dim3 grid(Nn / BN, Nn / BM, BATCH);   // (8, 4, 64)
    dim3 block(256);

    const __half* aP = c7H;
    long aStride = 0;
    __half* dstH[7] = {s0H, s1H, s0H, s1H, s0H, s1H, nullptr};

    for (int t = 0; t < 7; ++t) {
        const float* Ct = coeffs + (long)(6 - t) * 2 * NN;
        const int fin = (t == 6);
        cgemm_mma<<<grid, block, SMEM_BYTES>>>(
            aP, aStride, xtH, Ct,
            fin ? (float*)d_out : nullptr, dstH[t], fin);
        aP = dstH[t];
        aStride = 2L * NN;
    }
}